// round 10
// baseline (speedup 1.0000x reference)
#include <cuda_runtime.h>
#include <cuda_bf16.h>
#include <cstdint>

// x: (128, 512, 14, 14) fp32 ; W: (20, 512) fp32
// T=8, n=16, B=3136, c=512, H=4, K=5, O=20
#define NT   128
#define CCH  512
#define HWS  196
#define TT   8
#define NN   16
#define HH   4
#define KK   5
#define OO   20
#define BB   3136   // NN * HWS

// scratch: softmax weights, layout [h][t][k][B]  (coalesced at both ends)
__device__ float g_weights[(size_t)HH * TT * KK * BB];
#define GW_IDX(h, t, k, b) ((((size_t)(h) * TT + (t)) * KK + (k)) * BB + (b))

// ---------------- kernel 1: TF32 tensor-core logits + softmax ----------------
// grid = 256: blockIdx.x = nt*2 + half. half0 -> sp [0,96), half1 -> sp [96,196).
// 256 threads (8 warps). 8-buffer cp.async pipeline, 16-channel chunks,
// lookahead 7, ONE barrier per chunk.
#define KC      16                    // channels per staged chunk
#define NCHUNK  32                    // 512 / 16
#define NBUF    8
#define LOOKA   7                     // chunks staged ahead
#define APITCH  104                   // smem pitch (104%32==8 -> conflict-free)
#define ABUF    (KC * APITCH)         // 1664 floats per buffer
#define WPITCH  520                   // W smem pitch (conflict-free)
#define WROWS   24
#define SMEM1_BYTES ((NBUF * ABUF + WROWS * WPITCH) * 4)   // 53248+49920=103168

__device__ __forceinline__ uint32_t smem_u32(const void* p) {
    uint32_t a;
    asm("{ .reg .u64 t; cvta.to.shared.u64 t, %1; cvt.u32.u64 %0, t; }"
        : "=r"(a) : "l"(p));
    return a;
}

#define MMA_TF32(d, a0, a1, a2, a3, b0, b1)                                   \
    asm volatile("mma.sync.aligned.m16n8k8.row.col.f32.tf32.tf32.f32 "        \
                 "{%0,%1,%2,%3}, {%4,%5,%6,%7}, {%8,%9}, {%0,%1,%2,%3};"      \
                 : "+f"(d[0]), "+f"(d[1]), "+f"(d[2]), "+f"(d[3])             \
                 : "r"(a0), "r"(a1), "r"(a2), "r"(a3), "r"(b0), "r"(b1))

#define CP16(daddr, saddr)                                                    \
    asm volatile("cp.async.cg.shared.global [%0], [%1], 16;"                  \
                 :: "r"(daddr), "l"((const void*)(saddr)) : "memory")

__global__ void __launch_bounds__(256)
weights_mma_kernel(const float* __restrict__ x, const float* __restrict__ W)
{
    extern __shared__ float smem[];
    float* Abuf = smem;                    // [8][KC][APITCH]
    float* Wsh  = smem + NBUF * ABUF;      // [24][520] (rows 20..23 unused)

    const int tid  = threadIdx.x;
    const int bid  = blockIdx.x;
    const int nt   = bid >> 1;             // image 0..127
    const int half = bid & 1;
    const int off  = half * 96;            // global sp offset of this half
    const int nsp  = half ? 100 : 96;
    const int ntiles = half ? 7 : 6;       // m16 tiles

    const int w  = tid >> 5;
    const int l  = tid & 31;
    const int lg = l >> 2;                 // 0..7
    const int lc = l & 3;                  // 0..3

    // stage W rows (raw fp32; mma HW truncates to tf32)
    for (int i = tid; i < OO * CCH; i += 256) {
        const int n = i >> 9, k = i & (CCH - 1);
        Wsh[n * WPITCH + k] = W[i];
    }

    const float* xbase = x + (size_t)nt * CCH * HWS + off;
    const uint32_t abase_u32 = smem_u32(Abuf);

    // staging: compile-time divisor per half (no runtime IDIV)
    auto stage = [&](int ck) {
        const float* src = xbase + (size_t)ck * KC * HWS;
        const uint32_t dst0 = abase_u32 + (ck & (NBUF - 1)) * (ABUF * 4);
        if (half == 0) {
            for (int f = tid; f < KC * 24; f += 256) {
                const int c = f / 24, i = f - c * 24;
                CP16(dst0 + (c * APITCH + 4 * i) * 4, src + c * HWS + 4 * i);
            }
        } else {
            for (int f = tid; f < KC * 25; f += 256) {
                const int c = f / 25, i = f - c * 25;
                CP16(dst0 + (c * APITCH + 4 * i) * 4, src + c * HWS + 4 * i);
            }
        }
        asm volatile("cp.async.commit_group;" ::: "memory");
    };

    // one m16 tile per warp
    const bool tvalid = (w < ntiles);
    const int sp0 = 16 * w + lg;
    const int spa = min(sp0, APITCH - 1);       // clamped rows never stored
    const int spb = min(sp0 + 8, APITCH - 1);

    float d[3][4];
#pragma unroll
    for (int nf = 0; nf < 3; ++nf)
#pragma unroll
        for (int r = 0; r < 4; ++r) d[nf][r] = 0.f;

#pragma unroll
    for (int ck = 0; ck < LOOKA; ++ck) stage(ck);   // 7 chunks in flight

    for (int ck = 0; ck < NCHUNK; ++ck) {
        // exact wait: group for chunk ck complete.
        // staged_through = min(ck + LOOKA - 1, NCHUNK-1); N = staged_through - ck
        const int rem = NCHUNK - 1 - ck;
        if (rem >= 6)      { asm volatile("cp.async.wait_group 6;" ::: "memory"); }
        else if (rem == 5) { asm volatile("cp.async.wait_group 5;" ::: "memory"); }
        else if (rem == 4) { asm volatile("cp.async.wait_group 4;" ::: "memory"); }
        else if (rem == 3) { asm volatile("cp.async.wait_group 3;" ::: "memory"); }
        else if (rem == 2) { asm volatile("cp.async.wait_group 2;" ::: "memory"); }
        else if (rem == 1) { asm volatile("cp.async.wait_group 1;" ::: "memory"); }
        else               { asm volatile("cp.async.wait_group 0;" ::: "memory"); }
        __syncthreads();   // single barrier: also proves all warps finished
                           // reading buf (ck-1)%8 == (ck+LOOKA)%8 target

        const float* Ab = Abuf + (ck & (NBUF - 1)) * ABUF;
#pragma unroll
        for (int k8 = 0; k8 < KC / 8; ++k8) {
            const int kl = k8 * 8;
            const int kg = ck * KC + kl + lc;
            uint32_t bfr[3][2];
#pragma unroll
            for (int nf = 0; nf < 3; ++nf) {
                bfr[nf][0] = __float_as_uint(Wsh[(8 * nf + lg) * WPITCH + kg]);
                bfr[nf][1] = __float_as_uint(Wsh[(8 * nf + lg) * WPITCH + kg + 4]);
            }
            if (tvalid) {
                const float* r0 = Ab + (kl + lc) * APITCH;
                const float* r4 = Ab + (kl + lc + 4) * APITCH;
                const uint32_t a0 = __float_as_uint(r0[spa]);
                const uint32_t a1 = __float_as_uint(r0[spb]);
                const uint32_t a2 = __float_as_uint(r4[spa]);
                const uint32_t a3 = __float_as_uint(r4[spb]);
#pragma unroll
                for (int nf = 0; nf < 3; ++nf)
                    MMA_TF32(d[nf], a0, a1, a2, a3, bfr[nf][0], bfr[nf][1]);
            }
        }
        if (ck + LOOKA < NCHUNK) stage(ck + LOOKA);
    }

    // exchange D through smem (reuse Abuf region): Dx[112][24]
    __syncthreads();                 // all MMA reads done before overwrite
    float* Dx = smem;
    if (tvalid) {
        const int r = 16 * w + lg;
#pragma unroll
        for (int nf = 0; nf < 3; ++nf) {
            const int col = nf * 8 + 2 * lc;
            Dx[r * 24 + col]           = d[nf][0];
            Dx[r * 24 + col + 1]       = d[nf][1];
            Dx[(r + 8) * 24 + col]     = d[nf][2];
            Dx[(r + 8) * 24 + col + 1] = d[nf][3];
        }
    }
    __syncthreads();

    // per-position softmax; stores coalesced in [h][t][k][B] layout
    const int t_  = nt & (TT - 1);
    const int n_i = nt >> 3;
    for (int s = tid; s < nsp; s += 256) {
        const float* row = Dx + s * 24;
        const int b = n_i * HWS + off + s;
#pragma unroll
        for (int h = 0; h < HH; ++h) {
            float lo[KK];
#pragma unroll
            for (int k = 0; k < KK; ++k) lo[k] = row[h * KK + k];
            float m = lo[0];
#pragma unroll
            for (int k = 1; k < KK; ++k) m = fmaxf(m, lo[k]);
            float e[KK], sum = 0.f;
#pragma unroll
            for (int k = 0; k < KK; ++k) { e[k] = __expf(lo[k] - m); sum += e[k]; }
            const float inv = 1.f / sum;
#pragma unroll
            for (int k = 0; k < KK; ++k)
                g_weights[GW_IDX(h, t_, k, b)] = e[k] * inv;
        }
    }
}

// ---------------- kernel 2: causal 5-tap combine ----------------------------
// grid = (n_i : 16, ct : 64) ; block = 224 threads (196 active = spatial pos).
// Weights staged once into smem (coalesced), read via LDS in the loop ->
// lower register pressure -> 5 blocks/SM.
__global__ void __launch_bounds__(224, 5)
combine_kernel(const float* __restrict__ x, float* __restrict__ out)
{
    __shared__ float wsh[TT * KK][200];   // 40 rows x 196 (pad 200) = 32KB

    const int n_i = blockIdx.x;
    const int ct  = blockIdx.y;           // channel tile of 8
    const int h   = ct >> 4;
    const int tid = threadIdx.x;

    if (tid < HWS) {
        const int b = n_i * HWS + tid;
#pragma unroll
        for (int t = 0; t < TT; ++t)
#pragma unroll
            for (int k = 0; k < KK; ++k)
                wsh[t * KK + k][tid] = g_weights[GW_IDX(h, t, k, b)];
    }
    __syncthreads();

    const int sp = tid;
    if (sp >= HWS) return;

    const size_t tstride = (size_t)CCH * HWS;
    const size_t base = ((size_t)n_i * TT * CCH + (size_t)ct * 8) * HWS + sp;

#pragma unroll 1
    for (int cp = 0; cp < 4; ++cp) {
        const float* xp0 = x + base + (size_t)(2 * cp) * HWS;
        const float* xp1 = xp0 + HWS;
        float a[TT], bv[TT];
#pragma unroll
        for (int t = 0; t < TT; ++t) a[t]  = xp0[(size_t)t * tstride];
#pragma unroll
        for (int t = 0; t < TT; ++t) bv[t] = xp1[(size_t)t * tstride];

        float* op0 = out + base + (size_t)(2 * cp) * HWS;
        float* op1 = op0 + HWS;
#pragma unroll
        for (int t = 0; t < TT; ++t) {
            float s0 = 0.f, s1 = 0.f;
#pragma unroll
            for (int k = 0; k < KK; ++k) {
                const int src = t + k - 4;
                if (src >= 0) {
                    const float wv = wsh[t * KK + k][sp];
                    s0 = fmaf(wv, a[src],  s0);
                    s1 = fmaf(wv, bv[src], s1);
                }
            }
            op0[(size_t)t * tstride] = s0;
            op1[(size_t)t * tstride] = s1;
        }
    }
}

// ---------------------------------------------------------------------------
extern "C" void kernel_launch(void* const* d_in, const int* in_sizes, int n_in,
                              void* d_out, int out_size)
{
    const float* x = (const float*)d_in[0];
    const float* W = (const float*)d_in[1];
    float* out = (float*)d_out;

    cudaFuncSetAttribute(weights_mma_kernel,
                         cudaFuncAttributeMaxDynamicSharedMemorySize, SMEM1_BYTES);

    weights_mma_kernel<<<2 * NT, 256, SMEM1_BYTES>>>(x, W);
    combine_kernel<<<dim3(NN, 64), 224>>>(x, out);
}